// round 6
// baseline (speedup 1.0000x reference)
#include <cuda_runtime.h>
#include <cuda_bf16.h>
#include <math.h>
#include <stdint.h>

#define BATCH_N   4096
#define FEAT_D    512
#define NUM_AGES  100
#define EPS_F     1e-6f

#define TI 64
#define TJ 128
#define NJT (BATCH_N / TJ)                 // 32
#define NPAIR (NJT * NJT + NJT)            // 1056 tiles: J=0..31, I=0..2J+1
#define KC 128                             // K chunk (fp8) = 128B rows
#define NCHUNK (FEAT_D / KC)               // 4
#define STAGE_BYTES 40960                  // Zi 8KB + Zj 16KB + Wj 16KB
#define META 4096
#define SMEM_DYN (META + 2 * STAGE_BYTES + 1024)
#define WSCALE 16.0f

#define SW128(o) ((o) ^ (((o) >> 3) & 0x70))

// ---------------- device scratch ----------------
__device__ uint8_t g_z8[BATCH_N * FEAT_D];   // e4m3(z), age-sorted
__device__ uint8_t g_w8[BATCH_N * FEAT_D];   // e4m3(16*w), age-sorted
__device__ float  g_sq[BATCH_N];
__device__ float  g_dw[BATCH_N];             // 16 * (z . w)
__device__ int    g_ages[BATCH_N];           // ascending
__device__ int    g_perm[BATCH_N];
__device__ double g_acc;

// ---------------- PTX helpers ----------------
static __device__ __forceinline__ void ldsm_x4(uint32_t (&r)[4], uint32_t addr) {
    asm volatile("ldmatrix.sync.aligned.m8n8.x4.shared.b16 {%0,%1,%2,%3}, [%4];"
                 : "=r"(r[0]), "=r"(r[1]), "=r"(r[2]), "=r"(r[3]) : "r"(addr));
}
static __device__ __forceinline__ void mma_fp8(float (&c)[4], const uint32_t (&a)[4],
                                               const uint32_t b0, const uint32_t b1) {
    asm volatile(
        "mma.sync.aligned.m16n8k32.row.col.f32.e4m3.e4m3.f32 "
        "{%0,%1,%2,%3}, {%4,%5,%6,%7}, {%8,%9}, {%0,%1,%2,%3};"
        : "+f"(c[0]), "+f"(c[1]), "+f"(c[2]), "+f"(c[3])
        : "r"(a[0]), "r"(a[1]), "r"(a[2]), "r"(a[3]), "r"(b0), "r"(b1));
}
static __device__ __forceinline__ void cp16(uint32_t dst, const void* src) {
    asm volatile("cp.async.cg.shared.global [%0], [%1], 16;" :: "r"(dst), "l"(src) : "memory");
}
// pack 4 floats -> 4 e4m3 bytes (x0 in low byte)
static __device__ __forceinline__ uint32_t pack4_e4m3(float x0, float x1, float x2, float x3) {
    uint16_t lo, hi;
    asm("cvt.rn.satfinite.e4m3x2.f32 %0, %1, %2;" : "=h"(lo) : "f"(x1), "f"(x0));
    asm("cvt.rn.satfinite.e4m3x2.f32 %0, %1, %2;" : "=h"(hi) : "f"(x3), "f"(x2));
    return (uint32_t)lo | ((uint32_t)hi << 16);
}

// ---------------- K0: counting sort by age (loss is pair-permutation invariant) ----------------
__global__ __launch_bounds__(1024) void k_sort(const void* __restrict__ ages_raw) {
    __shared__ int s_is64;
    __shared__ int s_hist[NUM_AGES];
    __shared__ int s_off[NUM_AGES];
    const int t = threadIdx.x;
    if (t == 0) {
        const long long* p = (const long long*)ages_raw;
        int ok = 1;
        for (int q = 0; q < 64; ++q) {
            long long v = p[q];
            if (v < 0 || v >= NUM_AGES) { ok = 0; break; }
        }
        s_is64 = ok;
        g_acc = 0.0;
    }
    if (t < NUM_AGES) s_hist[t] = 0;
    __syncthreads();
    const int is64 = s_is64;

    for (int i = t; i < BATCH_N; i += 1024) {
        int a = is64 ? (int)((const long long*)ages_raw)[i]
                     : ((const int*)ages_raw)[i];
        atomicAdd(&s_hist[a], 1);
    }
    __syncthreads();
    if (t == 0) {
        int run = 0;
        for (int b = 0; b < NUM_AGES; ++b) { s_off[b] = run; run += s_hist[b]; }
    }
    __syncthreads();
    for (int i = t; i < BATCH_N; i += 1024) {
        int a = is64 ? (int)((const long long*)ages_raw)[i]
                     : ((const int*)ages_raw)[i];
        int pos = atomicAdd(&s_off[a], 1);
        g_perm[pos] = i;
        g_ages[pos] = a;
    }
}

// ---------------- K1: z8, w8(=16w), 16*dw, sq (sorted order) ----------------
// thread t handles the float4 at elem offset 4t.
__global__ __launch_bounds__(128) void k_prep(const float* __restrict__ z,
                                              const float* __restrict__ proxies) {
    const int j    = blockIdx.x;
    const int t    = threadIdx.x;
    const int orig = g_perm[j];
    const int aj = g_ages[j];
    const int an = min(aj + 1, NUM_AGES - 1);
    const int ap = max(aj - 1, 0);
    const float4* cc = (const float4*)(proxies + (size_t)aj * FEAT_D);
    const float4* cn = (const float4*)(proxies + (size_t)an * FEAT_D);
    const float4* cp = (const float4*)(proxies + (size_t)ap * FEAT_D);
    const float4* zr = (const float4*)(z + (size_t)orig * FEAT_D);

    float4 c4 = cc[t], n4 = cn[t], p4 = cp[t], z4 = zr[t];
    float df[4] = {n4.x - c4.x, n4.y - c4.y, n4.z - c4.z, n4.w - c4.w};
    float db[4] = {p4.x - c4.x, p4.y - c4.y, p4.z - c4.z, p4.w - c4.w};
    float zv[4] = {z4.x, z4.y, z4.z, z4.w};

    float nf2 = 0.f, nb2 = 0.f;
#pragma unroll
    for (int q = 0; q < 4; ++q) { nf2 += df[q] * df[q]; nb2 += db[q] * db[q]; }
#pragma unroll
    for (int o = 16; o; o >>= 1) {
        nf2 += __shfl_xor_sync(0xFFFFFFFFu, nf2, o);
        nb2 += __shfl_xor_sync(0xFFFFFFFFu, nb2, o);
    }
    __shared__ float sf[4], sb[4];
    if ((t & 31) == 0) { sf[t >> 5] = nf2; sb[t >> 5] = nb2; }
    __syncthreads();
    nf2 = sf[0] + sf[1] + sf[2] + sf[3];
    nb2 = sb[0] + sb[1] + sb[2] + sb[3];
    const float rf = 1.f / (sqrtf(nf2) + EPS_F);
    const float rb = 1.f / (sqrtf(nb2) + EPS_F);

    float wv[4];
    float dw = 0.f, sq = 0.f;
#pragma unroll
    for (int q = 0; q < 4; ++q) {
        wv[q] = db[q] * rb - df[q] * rf;
        dw += zv[q] * wv[q];
        sq += zv[q] * zv[q];
    }
    ((uint32_t*)g_z8)[(size_t)j * (FEAT_D / 4) + t] =
        pack4_e4m3(zv[0], zv[1], zv[2], zv[3]);
    ((uint32_t*)g_w8)[(size_t)j * (FEAT_D / 4) + t] =
        pack4_e4m3(wv[0] * WSCALE, wv[1] * WSCALE, wv[2] * WSCALE, wv[3] * WSCALE);

#pragma unroll
    for (int o = 16; o; o >>= 1) {
        dw += __shfl_xor_sync(0xFFFFFFFFu, dw, o);
        sq += __shfl_xor_sync(0xFFFFFFFFu, sq, o);
    }
    __shared__ float sd[4], ss[4];
    if ((t & 31) == 0) { sd[t >> 5] = dw; ss[t >> 5] = sq; }
    __syncthreads();
    if (t == 0) {
        g_dw[j] = (sd[0] + sd[1] + sd[2] + sd[3]) * WSCALE;
        g_sq[j] = ss[0] + ss[1] + ss[2] + ss[3];
    }
}

// ---------------- K2: dual-Gram FP8 HMMA, 64x128 tiles, 2 CTAs/SM ----------------
__global__ __launch_bounds__(128, 2) void k_main() {
    extern __shared__ char smem_raw[];
    uint32_t sbase;
    asm("{ .reg .u64 t; cvta.to.shared.u64 t, %1; cvt.u32.u64 %0, t; }"
        : "=r"(sbase) : "l"(smem_raw));
    const uint32_t abase = (sbase + 1023u) & ~1023u;
    char* ab = smem_raw + (abase - sbase);

    float* s_sqi  = (float*)(ab);            // 64
    int*   s_agi  = (int*)(ab + 256);        // 64
    float* s_sqj  = (float*)(ab + 512);      // 128
    float* s_dwj  = (float*)(ab + 1024);     // 128
    int*   s_agej = (int*)(ab + 1536);       // 128
    float* s_red  = (float*)(ab + 2048);     // 128

    // linear block -> (I, J): J has tiles I = 0..2J+1; cum(J) = J^2 + J
    int b = blockIdx.x;
    int J = (int)((sqrtf(4.0f * (float)b + 1.0f) - 1.0f) * 0.5f);
    while ((J + 1) * (J + 1) + (J + 1) <= b) ++J;
    while (J * J + J > b) --J;
    const int I  = b - (J * J + J);
    const int i0 = I * TI;
    const int j0 = J * TJ;

    const int tid  = threadIdx.x;
    const int lane = tid & 31;
    const int wn   = tid >> 5;   // 0..3

    if (tid < 64) {
        s_sqi[tid] = g_sq[i0 + tid];
        s_agi[tid] = g_ages[i0 + tid];
    }
    {
        s_sqj[tid]  = g_sq[j0 + tid];
        s_dwj[tid]  = g_dw[j0 + tid];
        s_agej[tid] = g_ages[j0 + tid];
    }

    const uint32_t stg0 = abase + META;

    auto load_stage = [&](int c) {
        uint32_t st = stg0 + (uint32_t)(c & 1) * STAGE_BYTES;
        int k0 = c * KC;   // byte offset within each row
#pragma unroll
        for (int q = 0; q < 4; ++q) {      // Zi: 512 units (64 rows x 8)
            int u = tid + q * 128;
            int row = u >> 3, un = u & 7;
            cp16(st + SW128((uint32_t)(u * 16)),
                 g_z8 + (size_t)(i0 + row) * FEAT_D + k0 + un * 16);
        }
#pragma unroll
        for (int q = 0; q < 8; ++q) {      // Zj + Wj: 1024 units each
            int u = tid + q * 128;
            int row = u >> 3, un = u & 7;
            uint32_t d = SW128((uint32_t)(u * 16));
            cp16(st + 8192  + d, g_z8 + (size_t)(j0 + row) * FEAT_D + k0 + un * 16);
            cp16(st + 24576 + d, g_w8 + (size_t)(j0 + row) * FEAT_D + k0 + un * 16);
        }
        asm volatile("cp.async.commit_group;" ::: "memory");
    };

    load_stage(0);
    load_stage(1);

    float cg[4][4][4] = {};
    float cw[4][4][4] = {};

    const int q8 = lane >> 3;
    const int lr = lane & 7;

#pragma unroll 1
    for (int c = 0; c < NCHUNK; ++c) {
        if (c == NCHUNK - 1) asm volatile("cp.async.wait_group 0;" ::: "memory");
        else                 asm volatile("cp.async.wait_group 1;" ::: "memory");
        __syncthreads();

        const uint32_t st = stg0 + (uint32_t)(c & 1) * STAGE_BYTES;
        const uint32_t zi = st, zj = st + 8192, wj = st + 24576;

#pragma unroll
        for (int kb = 0; kb < KC; kb += 32) {   // 32 fp8 elems = 32 bytes per k-step
            uint32_t a[4][4];
#pragma unroll
            for (int mt = 0; mt < 4; ++mt) {
                int row = mt * 16 + lr + (q8 & 1) * 8;
                int colb = kb + (q8 >> 1) * 16;
                ldsm_x4(a[mt], zi + SW128((uint32_t)(row * 128 + colb)));
            }
            uint32_t bz[4][2], bw[4][2];
#pragma unroll
            for (int p = 0; p < 2; ++p) {
                int row = wn * 32 + p * 16 + lr + (q8 >> 1) * 8;
                int colb = kb + (q8 & 1) * 16;
                uint32_t off = SW128((uint32_t)(row * 128 + colb));
                uint32_t rz[4], rw[4];
                ldsm_x4(rz, zj + off);
                ldsm_x4(rw, wj + off);
                bz[2 * p][0] = rz[0]; bz[2 * p][1] = rz[1];
                bz[2 * p + 1][0] = rz[2]; bz[2 * p + 1][1] = rz[3];
                bw[2 * p][0] = rw[0]; bw[2 * p][1] = rw[1];
                bw[2 * p + 1][0] = rw[2]; bw[2 * p + 1][1] = rw[3];
            }
#pragma unroll
            for (int mt = 0; mt < 4; ++mt)
#pragma unroll
                for (int nt = 0; nt < 4; ++nt) {
                    mma_fp8(cg[mt][nt], a[mt], bz[nt][0], bz[nt][1]);
                    mma_fp8(cw[mt][nt], a[mt], bw[nt][0], bw[nt][1]);
                }
        }

        __syncthreads();
        if (c + 2 < NCHUNK) load_stage(c + 2);
    }

    // ---- epilogue: masked softplus on register fragments ----
    // x = (Gw16 - dw16_j) * (10/16) / (||zi - zj|| + eps)
    const int g  = lane >> 2;
    const int tg = lane & 3;
    const float xs = 10.0f / WSCALE;
    float lsum = 0.f;
#pragma unroll
    for (int mt = 0; mt < 4; ++mt) {
        int r0 = mt * 16 + g;
        float sqi0 = s_sqi[r0],     sqi1 = s_sqi[r0 + 8];
        int   ag0  = s_agi[r0],     ag1  = s_agi[r0 + 8];
#pragma unroll
        for (int nt = 0; nt < 4; ++nt) {
            int cb = wn * 32 + nt * 8 + tg * 2;
#pragma unroll
            for (int h = 0; h < 2; ++h) {
                int cj = cb + h;
                float sqj = s_sqj[cj], dwj = s_dwj[cj];
                int   agj = s_agej[cj];
                if (ag0 < agj) {
                    float G  = cg[mt][nt][h];
                    float Gw = cw[mt][nt][h];
                    float d2 = fmaxf(sqi0 + sqj - 2.f * G, 0.f);
                    float x  = __fdividef((Gw - dwj) * xs, sqrtf(d2) + EPS_F);
                    lsum += fmaxf(x, 0.f) + __logf(1.f + __expf(-fabsf(x)));
                }
                if (ag1 < agj) {
                    float G  = cg[mt][nt][2 + h];
                    float Gw = cw[mt][nt][2 + h];
                    float d2 = fmaxf(sqi1 + sqj - 2.f * G, 0.f);
                    float x  = __fdividef((Gw - dwj) * xs, sqrtf(d2) + EPS_F);
                    lsum += fmaxf(x, 0.f) + __logf(1.f + __expf(-fabsf(x)));
                }
            }
        }
    }

    s_red[tid] = lsum;
    __syncthreads();
#pragma unroll
    for (int s = 64; s > 0; s >>= 1) {
        if (tid < s) s_red[tid] += s_red[tid + s];
        __syncthreads();
    }
    if (tid == 0) atomicAdd(&g_acc, (double)s_red[0]);
}

// ---------------- K3: finalize ----------------
__global__ void k_final(float* __restrict__ out) {
    out[0] = (float)(g_acc / ((double)BATCH_N * (double)(BATCH_N - 1)));
}

extern "C" void kernel_launch(void* const* d_in, const int* in_sizes, int n_in,
                              void* d_out, int out_size) {
    const float* z       = (const float*)d_in[0];
    const void*  ages    = d_in[1];
    const float* proxies = (const float*)d_in[2];
    float* out = (float*)d_out;

    cudaFuncSetAttribute(k_main, cudaFuncAttributeMaxDynamicSharedMemorySize, SMEM_DYN);

    k_sort<<<1, 1024>>>(ages);
    k_prep<<<BATCH_N, 128>>>(z, proxies);
    k_main<<<NPAIR, 128, SMEM_DYN>>>();
    k_final<<<1, 1>>>(out);
}